// round 1
// baseline (speedup 1.0000x reference)
#include <cuda_runtime.h>

#define HH 256
#define WW 256
#define BB 8
#define NGT 256
#define NPIX (HH*WW)

static __device__ __constant__ float kMAXD = 362.03867196751236f; // sqrt(256^2+256^2)
#define EPSF 1e-6f

// Persistent scratch (no allocations allowed)
__device__ float g_S[BB*NGT];   // per-(b,j) sum over pixels of (wd+eps)^-9
__device__ float g_t1[BB];      // per-b sum p*min_d
__device__ float g_np[BB];      // per-b sum p

// -------------------------------------------------------------------
__global__ void k_init() {
    int t = threadIdx.x;
#pragma unroll
    for (int i = 0; i < BB; i++) g_S[i*NGT + t] = 0.0f;
    if (t < BB) { g_t1[t] = 0.0f; g_np[t] = 0.0f; }
}

// -------------------------------------------------------------------
// term1: thread = pixel x within row blockIdx.x of image blockIdx.y.
// min over 256 gt points; per-block precomputed dy^2 in smem.
__global__ void __launch_bounds__(256) k_term1(const float* __restrict__ prob,
                                               const float* __restrict__ gt) {
    __shared__ float2 s_pt[NGT];   // (xj, dy2)
    __shared__ float s_c[8], s_p[8];
    const int row = blockIdx.x;
    const int b   = blockIdx.y;
    const int t   = threadIdx.x;

    float2 g = ((const float2*)gt)[b*NGT + t];   // (y_j, x_j)
    float dy = (float)row - g.x;
    s_pt[t] = make_float2(g.y, dy*dy);
    __syncthreads();

    const float xf = (float)t;
    float m = 3.4e38f;
#pragma unroll 8
    for (int j = 0; j < NGT; j++) {
        float2 pj = s_pt[j];
        float dx = xf - pj.x;
        m = fminf(m, fmaf(dx, dx, pj.y));
    }

    float p = prob[(b*HH + row)*WW + t];
    float c = p * sqrtf(m);

    // block reduce c and p
#pragma unroll
    for (int o = 16; o; o >>= 1) {
        c += __shfl_down_sync(0xFFFFFFFFu, c, o);
        p += __shfl_down_sync(0xFFFFFFFFu, p, o);
    }
    if ((t & 31) == 0) { s_c[t >> 5] = c; s_p[t >> 5] = p; }
    __syncthreads();
    if (t == 0) {
        float C = 0.0f, P = 0.0f;
#pragma unroll
        for (int i = 0; i < 8; i++) { C += s_c[i]; P += s_p[i]; }
        atomicAdd(&g_t1[b], C);
        atomicAdd(&g_np[b], P);
    }
}

// -------------------------------------------------------------------
// term2: thread = gt point j; block = (row, b). Per-thread register
// accumulator for sum over the row's 256 pixels of (wd+eps)^-9.
__global__ void __launch_bounds__(256) k_term2(const float* __restrict__ prob,
                                               const float* __restrict__ gt) {
    __shared__ float2 s_px[WW];    // (p, (1-p)*MAXD + EPS)
    const int row = blockIdx.x;
    const int b   = blockIdx.y;
    const int t   = threadIdx.x;

    float pv = prob[(b*HH + row)*WW + t];
    s_px[t] = make_float2(pv, fmaf(-pv, kMAXD, kMAXD) + EPSF);

    float2 g = ((const float2*)gt)[b*NGT + t];   // (y_j, x_j)
    float dy  = (float)row - g.x;
    float dy2 = dy * dy;
    float dx  = 0.0f - g.y;                      // x=0 minus x_j, +1 each iter
    __syncthreads();

    float acc = 0.0f;
#pragma unroll 4
    for (int x = 0; x < WW; x++) {
        float2 pb = s_px[x];
        float d2 = fmaf(dx, dx, dy2);
        d2 = fmaxf(d2, 1e-12f);              // guard rsqrt(0)
        float rs = rsqrtf(d2);
        float d  = d2 * rs;                  // sqrt(d2)
        float tt = fmaf(pb.x, d, pb.y);      // p*d + (1-p)*MAXD + EPS
        float iv = rsqrtf(tt);
        float i2 = iv * iv;                  // ~ 1/tt
        float a  = i2 * i2;                  // tt^-2
        float bb = a * a;                    // tt^-4
        float c8 = bb * bb;                  // tt^-8
        acc = fmaf(c8, i2, acc);             // += tt^-9
        dx += 1.0f;
    }
    atomicAdd(&g_S[b*NGT + t], acc);
}

// -------------------------------------------------------------------
__global__ void k_final(float* __restrict__ out) {
    __shared__ float sred[8];
    const int t = threadIdx.x;
    const float invA = -1.0f / 9.0f;
    float s = 0.0f;
#pragma unroll
    for (int b = 0; b < BB; b++) {
        float m = g_S[b*NGT + t] * (1.0f / (float)NPIX);
        s += powf(m, invA);
    }
#pragma unroll
    for (int o = 16; o; o >>= 1) s += __shfl_down_sync(0xFFFFFFFFu, s, o);
    if ((t & 31) == 0) sred[t >> 5] = s;
    __syncthreads();
    if (t == 0) {
        float T2 = 0.0f;
#pragma unroll
        for (int i = 0; i < 8; i++) T2 += sred[i];
        T2 *= (1.0f / (float)(BB * NGT));
        float T1 = 0.0f;
#pragma unroll
        for (int b = 0; b < BB; b++) T1 += g_t1[b] / (g_np[b] + EPSF);
        T1 *= (1.0f / (float)BB);
        out[0] = T1 + T2;
    }
}

// -------------------------------------------------------------------
extern "C" void kernel_launch(void* const* d_in, const int* in_sizes, int n_in,
                              void* d_out, int out_size) {
    const float* prob = (const float*)d_in[0];   // (B,1,H,W) f32
    const float* gt   = (const float*)d_in[1];   // (B,NGT,2) f32
    float* out = (float*)d_out;

    k_init<<<1, 256>>>();
    dim3 grid(HH, BB);
    k_term1<<<grid, 256>>>(prob, gt);
    k_term2<<<grid, 256>>>(prob, gt);
    k_final<<<1, 256>>>(out);
}

// round 5
// speedup vs baseline: 1.1494x; 1.1494x over previous
#include <cuda_runtime.h>

#define HH 256
#define WW 256
#define BB 8
#define NGT 256
#define NPIX (HH*WW)

static __device__ __constant__ float kMAXD = 362.03867196751236f; // sqrt(256^2+256^2)
#define EPSF 1e-6f

// Persistent scratch (no allocations allowed)
__device__ float g_S[BB*NGT];   // per-(b,j) sum over pixels of (wd+eps)^-9
__device__ float g_t1[BB];      // per-b sum p*min_d
__device__ float g_np[BB];      // per-b sum p

__device__ __forceinline__ float sqrt_approx(float x) {
    float r;
    asm("sqrt.approx.f32 %0, %1;" : "=f"(r) : "f"(x));
    return r;
}
__device__ __forceinline__ float rcp_approx(float x) {
    float r;
    asm("rcp.approx.f32 %0, %1;" : "=f"(r) : "f"(x));
    return r;
}
__device__ __forceinline__ float lg2_approx(float x) {
    float r;
    asm("lg2.approx.f32 %0, %1;" : "=f"(r) : "f"(x));
    return r;
}
__device__ __forceinline__ float ex2_approx(float x) {
    float r;
    asm("ex2.approx.f32 %0, %1;" : "=f"(r) : "f"(x));
    return r;
}

// -------------------------------------------------------------------
__global__ void k_init() {
    int t = threadIdx.x;
#pragma unroll
    for (int i = 0; i < BB; i++) g_S[i*NGT + t] = 0.0f;
    if (t < BB) { g_t1[t] = 0.0f; g_np[t] = 0.0f; }
}

// -------------------------------------------------------------------
// Fused kernel. Block = (row, b), 256 threads.
//  Phase A (term2, MUFU-bound): thread = gt point j, loop over the row's
//    256 pixels, accumulate (p*d + (1-p)*M + eps)^-9 in a register.
//  Phase B (term1, issue-bound, hides under phase A's MUFU across warps):
//    thread = pixel x, min over 256 gt points of d^2, then p*sqrt(min).
__global__ void __launch_bounds__(256) k_fused(const float* __restrict__ prob,
                                               const float* __restrict__ gt) {
    __shared__ float2 s_px[WW];    // (p, (1-p)*MAXD + EPS)
    __shared__ float2 s_pt[NGT];   // (x_j, dy^2)
    __shared__ float s_c[8], s_p[8];

    const int row = blockIdx.x;
    const int b   = blockIdx.y;
    const int t   = threadIdx.x;

    // per-thread gt point j = t
    float2 g  = ((const float2*)gt)[b*NGT + t];   // (y_j, x_j)
    float dy  = (float)row - g.x;
    float dy2 = dy * dy;
    s_pt[t] = make_float2(g.y, dy2);

    // per-thread pixel x = t
    float p = prob[(b*HH + row)*WW + t];
    float c = fmaf(-p, kMAXD, kMAXD) + EPSF;      // (1-p)*M + eps
    s_px[t] = make_float2(p, c);
    __syncthreads();

    // ---- Phase A: term2 ----
    float dy2e = dy2 + 1e-18f;     // folds the rsqrt(0) guard for free
    float dx   = 0.0f - g.y;       // x=0 minus x_j; +1 each iteration
    float acc  = 0.0f;
#pragma unroll 16
    for (int x = 0; x < WW; x++) {
        float2 pb = s_px[x];                 // broadcast LDS.64
        float d2  = fmaf(dx, dx, dy2e);
        float d   = sqrt_approx(d2);         // MUFU.SQRT
        float tt  = fmaf(pb.x, d, pb.y);     // p*d + (1-p)*M + eps
        float iv  = rcp_approx(tt);          // MUFU.RCP  -> tt^-1
        float i2  = iv * iv;
        float i4  = i2 * i2;
        float i8  = i4 * i4;
        acc = fmaf(i8, iv, acc);             // += tt^-9
        dx += 1.0f;
    }
    atomicAdd(&g_S[b*NGT + t], acc);

    // ---- Phase B: term1 ----
    const float xf = (float)t;
    float m = 3.4e38f;
#pragma unroll 16
    for (int j = 0; j < NGT; j++) {
        float2 pj = s_pt[j];
        float dxx = xf - pj.x;
        m = fminf(m, fmaf(dxx, dxx, pj.y));
    }
    float cterm = p * sqrt_approx(m);

    float pr = p;
#pragma unroll
    for (int o = 16; o; o >>= 1) {
        cterm += __shfl_down_sync(0xFFFFFFFFu, cterm, o);
        pr    += __shfl_down_sync(0xFFFFFFFFu, pr, o);
    }
    if ((t & 31) == 0) { s_c[t >> 5] = cterm; s_p[t >> 5] = pr; }
    __syncthreads();
    if (t == 0) {
        float C = 0.0f, P = 0.0f;
#pragma unroll
        for (int i = 0; i < 8; i++) { C += s_c[i]; P += s_p[i]; }
        atomicAdd(&g_t1[b], C);
        atomicAdd(&g_np[b], P);
    }
}

// -------------------------------------------------------------------
__global__ void k_final(float* __restrict__ out) {
    __shared__ float sred[8];
    const int t = threadIdx.x;
    const float invA = -1.0f / 9.0f;
    float s = 0.0f;
#pragma unroll
    for (int b = 0; b < BB; b++) {
        float m = g_S[b*NGT + t] * (1.0f / (float)NPIX);
        s += ex2_approx(lg2_approx(m) * invA);   // m^(-1/9), 2x MUFU
    }
#pragma unroll
    for (int o = 16; o; o >>= 1) s += __shfl_down_sync(0xFFFFFFFFu, s, o);
    if ((t & 31) == 0) sred[t >> 5] = s;
    __syncthreads();
    if (t == 0) {
        float T2 = 0.0f;
#pragma unroll
        for (int i = 0; i < 8; i++) T2 += sred[i];
        T2 *= (1.0f / (float)(BB * NGT));
        float T1 = 0.0f;
#pragma unroll
        for (int b = 0; b < BB; b++) T1 += g_t1[b] / (g_np[b] + EPSF);
        T1 *= (1.0f / (float)BB);
        out[0] = T1 + T2;
    }
}

// -------------------------------------------------------------------
extern "C" void kernel_launch(void* const* d_in, const int* in_sizes, int n_in,
                              void* d_out, int out_size) {
    const float* prob = (const float*)d_in[0];   // (B,1,H,W) f32
    const float* gt   = (const float*)d_in[1];   // (B,NGT,2) f32
    float* out = (float*)d_out;

    k_init<<<1, 256>>>();
    dim3 grid(HH, BB);
    k_fused<<<grid, 256>>>(prob, gt);
    k_final<<<1, 256>>>(out);
}